// round 1
// baseline (speedup 1.0000x reference)
#include <cuda_runtime.h>
#include <cstdint>
#include <math.h>

#define BB   4
#define NQ   384
#define NK   384
#define DE   64
#define DQI  256
#define DKI  256
#define DM   64
#define DFF  256
#define DOUT 64

#define XH_STRIDE 260   // 128 x 260 fp32 tile (X for GEMM1, then h for GEMM2)
#define W2_STRIDE 68

// scratch (device globals -- no allocations allowed)
__device__ float g_Aq[BB * NQ * DFF];     // b1 + q_msg @ W1[0:64,:]
__device__ float g_kmsg[BB * NK * DM];    // k_inv @ Wk + bk

__device__ __forceinline__ float ftf32(float x) {
    uint32_t u;
    asm("cvt.rna.tf32.f32 %0, %1;" : "=r"(u) : "f"(x));
    return __uint_as_float(u);
}
__device__ __forceinline__ uint32_t fbits(float x) { return __float_as_uint(x); }

__device__ __forceinline__ void mma8(float* d, const uint32_t* a, uint32_t b0, uint32_t b1) {
    asm volatile(
        "mma.sync.aligned.m16n8k8.row.col.f32.tf32.tf32.f32 "
        "{%0,%1,%2,%3}, {%4,%5,%6,%7}, {%8,%9}, {%0,%1,%2,%3};"
        : "+f"(d[0]), "+f"(d[1]), "+f"(d[2]), "+f"(d[3])
        : "r"(a[0]), "r"(a[1]), "r"(a[2]), "r"(a[3]), "r"(b0), "r"(b1));
}

// ---------- precompute: Aq = b1 + (q_inv@Wq + bq) @ W1[0:64,:] ----------
__global__ void prep_q(const float* __restrict__ q_inv, const float* __restrict__ Wq,
                       const float* __restrict__ bq, const float* __restrict__ W1,
                       const float* __restrict__ b1) {
    const int bqi = blockIdx.x;                // 0 .. B*NQ-1
    __shared__ float sq[DQI];
    __shared__ float smg[DM];
    const int tid = threadIdx.x;               // 256
    sq[tid] = q_inv[(size_t)bqi * DQI + tid];
    __syncthreads();
    if (tid < DM) {
        float s = bq[tid];
        #pragma unroll 8
        for (int i = 0; i < DQI; i++) s += sq[i] * Wq[i * DM + tid];
        smg[tid] = s;
    }
    __syncthreads();
    float a = b1[tid];
    #pragma unroll 8
    for (int m = 0; m < DM; m++) a += smg[m] * W1[m * DFF + tid];
    g_Aq[(size_t)bqi * DFF + tid] = a;
}

// ---------- precompute: k_msg = k_inv@Wk + bk ----------
__global__ void prep_k(const float* __restrict__ k_inv, const float* __restrict__ Wk,
                       const float* __restrict__ bk) {
    const int bki = blockIdx.x;                // 0 .. B*NK-1
    __shared__ float sk[DKI];
    const int tid = threadIdx.x;               // 64
    for (int i = tid; i < DKI; i += 64) sk[i] = k_inv[(size_t)bki * DKI + i];
    __syncthreads();
    float s = bk[tid];
    #pragma unroll 8
    for (int i = 0; i < DKI; i++) s += sk[i] * Wk[i * DM + tid];
    g_kmsg[(size_t)bki * DM + tid] = s;
}

// ---------- main fused kernel: one CTA = (b, q, 128-k tile) ----------
__global__ __launch_bounds__(512, 1)
void pm_main(const float* __restrict__ q_equi, const float* __restrict__ k_equi,
             const float* __restrict__ W1, const float* __restrict__ W2,
             const float* __restrict__ b2, float* __restrict__ out) {
    extern __shared__ float smem[];
    float* XH  = smem;                               // [128][260]  X, later h
    float* Ws  = XH + 128 * XH_STRIDE;               // [2][8][260] W1 K-slice double buffer
    float* W2s = Ws + 2 * 8 * XH_STRIDE;             // [256][68]
    float* Aqs = W2s + 256 * W2_STRIDE;              // [256]
    float* b2s = Aqs + 256;                          // [64]
    float* qsm = b2s + 64;                           // [3*64]

    const int kb  = blockIdx.x;      // 0..2
    const int q   = blockIdx.y;      // 0..383
    const int b   = blockIdx.z;      // 0..3
    const int tid = threadIdx.x;     // 512
    const int kbase = kb * 128;
    const int bq = b * NQ + q;

    // ---- phase 0: stage smem ----
    if (tid < 192) qsm[tid] = q_equi[(size_t)bq * 192 + tid];
    if (tid < 256) Aqs[tid] = g_Aq[(size_t)bq * DFF + tid];
    else if (tid < 320) b2s[tid - 256] = b2[tid - 256];
    for (int i = tid; i < DFF * DOUT; i += 512) {
        int r = i >> 6, c = i & 63;
        W2s[r * W2_STRIDE + c] = ftf32(W2[i]);
    }
    for (int i = tid; i < 128 * 64; i += 512) {
        int kk = i >> 6, e = i & 63;
        XH[kk * XH_STRIDE + e] = ftf32(g_kmsg[(size_t)(b * NK + kbase + kk) * DM + e]);
    }
    // preload W1' K-slice 0 (W1 rows 64..255 = [k_msg | dot | dist] block)
    const int lr = (tid * 4) >> 8, lc = (tid * 4) & 255;
    {
        float4 v = *(const float4*)&W1[(size_t)(64 + lr) * DFF + lc];
        float* d = Ws + lr * XH_STRIDE + lc;
        d[0] = ftf32(v.x); d[1] = ftf32(v.y); d[2] = ftf32(v.z); d[3] = ftf32(v.w);
    }
    __syncthreads();

    // ---- phase 1: dot & dist (each thread owns one e, 16 k-rows) ----
    {
        const int e = tid & 63, kk0 = tid >> 6;
        const float q0 = qsm[e], q1 = qsm[64 + e], q2 = qsm[128 + e];
        const float qn2 = q0 * q0 + q1 * q1 + q2 * q2;
        const float* kp0 = k_equi + (size_t)(b * NK + kbase) * 192 + e;
        #pragma unroll 4
        for (int j = 0; j < 16; j++) {
            int kk = kk0 + j * 8;
            const float* kp = kp0 + (size_t)kk * 192;
            float k0 = kp[0], k1 = kp[64], k2 = kp[128];
            float dot = q0 * k0 + q1 * k1 + q2 * k2;
            float kn2 = k0 * k0 + k1 * k1 + k2 * k2;
            float dist = sqrtf(fmaxf(qn2 + kn2 - 2.0f * dot, 0.0f));
            XH[kk * XH_STRIDE + 64 + e]  = ftf32(dot);
            XH[kk * XH_STRIDE + 128 + e] = ftf32(dist);
        }
    }

    const int warp = tid >> 5, lane = tid & 31, g = lane >> 2, t = lane & 3;

    // ---- GEMM1: [128 x 192] @ [192 x 256], warps 4(M) x 4(N), tile 32x64 ----
    const int m0 = (warp >> 2) * 32, n0 = (warp & 3) * 64;
    float c1[2][8][4];
    #pragma unroll
    for (int mi = 0; mi < 2; mi++)
        #pragma unroll
        for (int ni = 0; ni < 8; ni++)
            #pragma unroll
            for (int z = 0; z < 4; z++) c1[mi][ni][z] = 0.f;

    for (int ks = 0; ks < 24; ks++) {
        __syncthreads();   // slice ks (buf ks&1) visible; prior readers of other buf done
        float4 stv;
        const bool ld = (ks + 1 < 24);
        if (ld) stv = *(const float4*)&W1[(size_t)(64 + (ks + 1) * 8 + lr) * DFF + lc];

        const float* wb = Ws + (ks & 1) * (8 * XH_STRIDE);
        uint32_t a[2][4];
        #pragma unroll
        for (int mi = 0; mi < 2; mi++) {
            const float* r0p = XH + (m0 + mi * 16 + g) * XH_STRIDE + ks * 8;
            const float* r1p = r0p + 8 * XH_STRIDE;
            a[mi][0] = fbits(r0p[t]);     a[mi][1] = fbits(r1p[t]);
            a[mi][2] = fbits(r0p[t + 4]); a[mi][3] = fbits(r1p[t + 4]);
        }
        uint32_t bb0[8], bb1[8];
        #pragma unroll
        for (int ni = 0; ni < 8; ni++) {
            bb0[ni] = fbits(wb[t * XH_STRIDE + n0 + ni * 8 + g]);
            bb1[ni] = fbits(wb[(t + 4) * XH_STRIDE + n0 + ni * 8 + g]);
        }
        #pragma unroll
        for (int mi = 0; mi < 2; mi++)
            #pragma unroll
            for (int ni = 0; ni < 8; ni++)
                mma8(c1[mi][ni], a[mi], bb0[ni], bb1[ni]);

        if (ld) {
            float* d = Ws + ((ks + 1) & 1) * (8 * XH_STRIDE) + lr * XH_STRIDE + lc;
            d[0] = ftf32(stv.x); d[1] = ftf32(stv.y); d[2] = ftf32(stv.z); d[3] = ftf32(stv.w);
        }
    }
    __syncthreads();   // all warps done reading X before h overwrites it

    // ---- epilogue 1: + Aq, silu, write h (tf32-rounded) into XH cols 0..255 ----
    #pragma unroll
    for (int mi = 0; mi < 2; mi++) {
        #pragma unroll
        for (int ni = 0; ni < 8; ni++) {
            int r0 = m0 + mi * 16 + g, r1 = r0 + 8;
            int f0 = n0 + ni * 8 + t * 2;
            float p00 = c1[mi][ni][0] + Aqs[f0];
            float p01 = c1[mi][ni][1] + Aqs[f0 + 1];
            float p10 = c1[mi][ni][2] + Aqs[f0];
            float p11 = c1[mi][ni][3] + Aqs[f0 + 1];
            p00 = p00 / (1.f + __expf(-p00));
            p01 = p01 / (1.f + __expf(-p01));
            p10 = p10 / (1.f + __expf(-p10));
            p11 = p11 / (1.f + __expf(-p11));
            XH[r0 * XH_STRIDE + f0]     = ftf32(p00);
            XH[r0 * XH_STRIDE + f0 + 1] = ftf32(p01);
            XH[r1 * XH_STRIDE + f0]     = ftf32(p10);
            XH[r1 * XH_STRIDE + f0 + 1] = ftf32(p11);
        }
    }
    __syncthreads();

    // ---- GEMM2: [128 x 256] @ [256 x 64], warps 8(M) x 2(N), tile 16x32 ----
    const int m2 = (warp >> 1) * 16, n2 = (warp & 1) * 32;
    float c2[4][4];
    #pragma unroll
    for (int ni = 0; ni < 4; ni++)
        #pragma unroll
        for (int z = 0; z < 4; z++) c2[ni][z] = 0.f;

    #pragma unroll 4
    for (int ku = 0; ku < 32; ku++) {
        uint32_t a[4];
        const float* r0p = XH + (m2 + g) * XH_STRIDE + ku * 8;
        const float* r1p = r0p + 8 * XH_STRIDE;
        a[0] = fbits(r0p[t]);     a[1] = fbits(r1p[t]);
        a[2] = fbits(r0p[t + 4]); a[3] = fbits(r1p[t + 4]);
        #pragma unroll
        for (int ni = 0; ni < 4; ni++) {
            uint32_t b0 = fbits(W2s[(ku * 8 + t) * W2_STRIDE + n2 + ni * 8 + g]);
            uint32_t b1 = fbits(W2s[(ku * 8 + t + 4) * W2_STRIDE + n2 + ni * 8 + g]);
            mma8(c2[ni], a, b0, b1);
        }
    }

    // ---- epilogue 2: + b2, store ----
    size_t obase = ((size_t)bq * NK + kbase) * DOUT;
    #pragma unroll
    for (int ni = 0; ni < 4; ni++) {
        int o = n2 + ni * 8 + t * 2;
        int r0 = m2 + g, r1 = r0 + 8;
        float2 v0 = make_float2(c2[ni][0] + b2s[o], c2[ni][1] + b2s[o + 1]);
        float2 v1 = make_float2(c2[ni][2] + b2s[o], c2[ni][3] + b2s[o + 1]);
        *(float2*)(out + obase + (size_t)r0 * DOUT + o) = v0;
        *(float2*)(out + obase + (size_t)r1 * DOUT + o) = v1;
    }
}

extern "C" void kernel_launch(void* const* d_in, const int* in_sizes, int n_in,
                              void* d_out, int out_size) {
    const float* q_equi = (const float*)d_in[0];
    const float* q_inv  = (const float*)d_in[1];
    const float* k_equi = (const float*)d_in[2];
    const float* k_inv  = (const float*)d_in[3];
    const float* Wq     = (const float*)d_in[4];
    const float* bq     = (const float*)d_in[5];
    const float* Wk     = (const float*)d_in[6];
    const float* bk     = (const float*)d_in[7];
    const float* W1     = (const float*)d_in[8];
    const float* b1     = (const float*)d_in[9];
    const float* W2     = (const float*)d_in[10];
    const float* b2     = (const float*)d_in[11];
    float* out = (float*)d_out;

    const int SMEM = (128 * XH_STRIDE + 2 * 8 * XH_STRIDE + 256 * W2_STRIDE
                      + 256 + 64 + 192) * (int)sizeof(float);   // ~216.5 KB
    cudaFuncSetAttribute(pm_main, cudaFuncAttributeMaxDynamicSharedMemorySize, SMEM);

    prep_q<<<BB * NQ, 256>>>(q_inv, Wq, bq, W1, b1);
    prep_k<<<BB * NK, 64>>>(k_inv, Wk, bk);
    pm_main<<<dim3(3, NQ, BB), 512, SMEM>>>(q_equi, k_equi, W1, W2, b2, out);
}

// round 3
// speedup vs baseline: 1.5810x; 1.5810x over previous
#include <cuda_runtime.h>
#include <cstdint>
#include <math.h>

#define BB   4
#define NQ   384
#define NK   384
#define DQI  256
#define DKI  256
#define DM   64
#define DFF  256
#define DOUT 64

#define S_X 132     // X stride (floats)
#define S_H 260     // h stride (floats)

#define OFF_H   0         // 133120 B : X (stride 132) then h (stride 260)
#define OFF_W1  133120    // 3 x 8320 B ring of W1 K-slices
#define OFF_W2  158080    // 69632 B packed W2
#define OFF_AQ  227712    // 1024 B
#define OFF_QS  228736    // 768 B
#define OFF_B2  229504    // 256 B
#define SMEM_BYTES 229760

// ---------------- device scratch ----------------
__device__ float g_Aq[BB * NQ * DFF];     // b1 + (q_inv@Wq+bq) @ W1[0:64,:]
__device__ float g_Bk[BB * NK * DFF];     // (k_inv@Wk+bk) @ W1[64:128,:]
__device__ float g_W1p[16 * 4 * 520];     // packed tf32 W1[128:256,:]  B-frag layout
__device__ float g_W2p[32 * 4 * 136];     // packed tf32 W2             B-frag layout

// ---------------- helpers ----------------
__device__ __forceinline__ float ftf32(float x) {
    uint32_t u;
    asm("cvt.rna.tf32.f32 %0, %1;" : "=r"(u) : "f"(x));
    return __uint_as_float(u);
}
__device__ __forceinline__ uint32_t fbits(float x) { return __float_as_uint(x); }

__device__ __forceinline__ uint32_t smem_u32(const void* p) {
    uint32_t a;
    asm("{ .reg .u64 t; cvta.to.shared.u64 t, %1; cvt.u32.u64 %0, t; }" : "=r"(a) : "l"(p));
    return a;
}

__device__ __forceinline__ void mma8(float* d, const uint32_t* a, uint32_t b0, uint32_t b1) {
    asm volatile(
        "mma.sync.aligned.m16n8k8.row.col.f32.tf32.tf32.f32 "
        "{%0,%1,%2,%3}, {%4,%5,%6,%7}, {%8,%9}, {%0,%1,%2,%3};"
        : "+f"(d[0]), "+f"(d[1]), "+f"(d[2]), "+f"(d[3])
        : "r"(a[0]), "r"(a[1]), "r"(a[2]), "r"(a[3]), "r"(b0), "r"(b1));
}

#define CP16(d, s) asm volatile("cp.async.cg.shared.global [%0], [%1], 16;" :: "r"(d), "l"(s))
#define CPCOMMIT() asm volatile("cp.async.commit_group;")
#define CPWAIT(n)  asm volatile("cp.async.wait_group %0;" :: "n"(n))

// ---------------- prep kernels ----------------
__global__ void prep_q(const float* __restrict__ q_inv, const float* __restrict__ Wq,
                       const float* __restrict__ bq, const float* __restrict__ W1,
                       const float* __restrict__ b1) {
    const int bqi = blockIdx.x, tid = threadIdx.x;   // 256 threads
    __shared__ float sq[DQI];
    __shared__ float sm[DM];
    sq[tid] = q_inv[(size_t)bqi * DQI + tid];
    __syncthreads();
    if (tid < DM) {
        float a0 = 0.f, a1 = 0.f, a2 = 0.f, a3 = 0.f;
        #pragma unroll 16
        for (int i = 0; i < DQI; i += 4) {
            a0 += sq[i]     * Wq[(size_t)i * DM + tid];
            a1 += sq[i + 1] * Wq[(size_t)(i + 1) * DM + tid];
            a2 += sq[i + 2] * Wq[(size_t)(i + 2) * DM + tid];
            a3 += sq[i + 3] * Wq[(size_t)(i + 3) * DM + tid];
        }
        sm[tid] = bq[tid] + ((a0 + a1) + (a2 + a3));
    }
    __syncthreads();
    float a0 = 0.f, a1 = 0.f, a2 = 0.f, a3 = 0.f;
    #pragma unroll 16
    for (int m = 0; m < DM; m += 4) {
        a0 += sm[m]     * W1[(size_t)m * DFF + tid];
        a1 += sm[m + 1] * W1[(size_t)(m + 1) * DFF + tid];
        a2 += sm[m + 2] * W1[(size_t)(m + 2) * DFF + tid];
        a3 += sm[m + 3] * W1[(size_t)(m + 3) * DFF + tid];
    }
    g_Aq[(size_t)bqi * DFF + tid] = b1[tid] + ((a0 + a1) + (a2 + a3));
}

__global__ void prep_kb(const float* __restrict__ k_inv, const float* __restrict__ Wk,
                        const float* __restrict__ bk, const float* __restrict__ W1) {
    const int bki = blockIdx.x, tid = threadIdx.x;   // 256 threads
    __shared__ float sk[DKI];
    __shared__ float sm[DM];
    sk[tid] = k_inv[(size_t)bki * DKI + tid];
    __syncthreads();
    if (tid < DM) {
        float a0 = 0.f, a1 = 0.f, a2 = 0.f, a3 = 0.f;
        #pragma unroll 16
        for (int i = 0; i < DKI; i += 4) {
            a0 += sk[i]     * Wk[(size_t)i * DM + tid];
            a1 += sk[i + 1] * Wk[(size_t)(i + 1) * DM + tid];
            a2 += sk[i + 2] * Wk[(size_t)(i + 2) * DM + tid];
            a3 += sk[i + 3] * Wk[(size_t)(i + 3) * DM + tid];
        }
        sm[tid] = bk[tid] + ((a0 + a1) + (a2 + a3));
    }
    __syncthreads();
    float a0 = 0.f, a1 = 0.f, a2 = 0.f, a3 = 0.f;
    #pragma unroll 16
    for (int m = 0; m < DM; m += 4) {
        a0 += sm[m]     * W1[(size_t)(64 + m) * DFF + tid];
        a1 += sm[m + 1] * W1[(size_t)(65 + m) * DFF + tid];
        a2 += sm[m + 2] * W1[(size_t)(66 + m) * DFF + tid];
        a3 += sm[m + 3] * W1[(size_t)(67 + m) * DFF + tid];
    }
    g_Bk[(size_t)bki * DFF + tid] = (a0 + a1) + (a2 + a3);
}

// pack W1[128:256,:] and W2 into B-fragment layouts, tf32-rounded
__global__ void prep_pack(const float* __restrict__ W1, const float* __restrict__ W2) {
    const int gid = blockIdx.x * 256 + threadIdx.x;
    if (gid < 16 * 4 * 520) {
        int s = gid / 2080, r = gid % 2080, t = r / 520, x = r % 520;
        float v = 0.f;
        if (x < 512) {
            int n = x >> 1, hi = x & 1;
            int k = 8 * s + t + 4 * hi;
            v = ftf32(W1[(size_t)(128 + k) * DFF + n]);
        }
        g_W1p[gid] = v;
    } else {
        int h = gid - 16 * 4 * 520;
        if (h < 32 * 4 * 136) {
            int ku = h / 544, r = h % 544, t = r / 136, x = r % 136;
            float v = 0.f;
            if (x < 128) {
                int n = x >> 1, hi = x & 1;
                int f = 8 * ku + t + 4 * hi;
                v = ftf32(W2[(size_t)f * DOUT + n]);
            }
            g_W2p[h] = v;
        }
    }
}

// ---------------- main kernel: one CTA = (b, q, 128-k tile) ----------------
__global__ __launch_bounds__(512, 1)
void pm_main(const float* __restrict__ q_equi, const float* __restrict__ k_equi,
             const float* __restrict__ b2, float* __restrict__ out) {
    extern __shared__ char smem[];
    float* H   = (float*)smem;
    float* Aqs = (float*)(smem + OFF_AQ);
    float* qs  = (float*)(smem + OFF_QS);
    float* b2s = (float*)(smem + OFF_B2);
    const float* W2s = (const float*)(smem + OFF_W2);
    const uint32_t sb = smem_u32(smem);

    const int kb = blockIdx.x, q = blockIdx.y, b = blockIdx.z;
    const int kbase = kb * 128, bq = b * NQ + q;
    const int tid = threadIdx.x, w = tid >> 5, lane = tid & 31;
    const int g = lane >> 2, t = lane & 3;

    // ---- prologue: prefetch W1 slices 0,1 ----
    {
        uint32_t d0 = sb + OFF_W1 + tid * 16;
        const char* s0 = (const char*)g_W1p + tid * 16;
        CP16(d0, s0);
        if (tid < 8) CP16(d0 + 8192, s0 + 8192);
        CPCOMMIT();
        uint32_t d1 = sb + OFF_W1 + 8320 + tid * 16;
        const char* s1 = (const char*)g_W1p + 8320 + tid * 16;
        CP16(d1, s1);
        if (tid < 8) CP16(d1 + 8192, s1 + 8192);
        CPCOMMIT();
    }
    if (tid < 192) qs[tid] = q_equi[(size_t)bq * 192 + tid];
    if (tid < 256) Aqs[tid] = g_Aq[(size_t)bq * DFF + tid];
    else if (tid < 320) b2s[tid - 256] = b2[tid - 256];
    __syncthreads();

    // ---- build X = [dot | dist] (tf32), row-major stride 132 ----
    {
        const int e = tid & 63, kk0 = tid >> 6;
        const float q0 = qs[e], q1 = qs[64 + e], q2 = qs[128 + e];
        const float qn2 = q0 * q0 + q1 * q1 + q2 * q2;
        const float* kp0 = k_equi + (size_t)(b * NK + kbase) * 192 + e;
        #pragma unroll 4
        for (int j = 0; j < 16; j++) {
            int kk = kk0 + j * 8;
            const float* kp = kp0 + (size_t)kk * 192;
            float k0 = kp[0], k1 = kp[64], k2 = kp[128];
            float dot = q0 * k0 + q1 * k1 + q2 * k2;
            float kn2 = k0 * k0 + k1 * k1 + k2 * k2;
            float dist = sqrtf(fmaxf(qn2 + kn2 - 2.f * dot, 0.f));
            H[kk * S_X + e]      = ftf32(dot);
            H[kk * S_X + 64 + e] = ftf32(dist);
        }
    }
    __syncthreads();

    // ---- GEMM1: [128x128] @ [128x256], warps 4M x 4N (32x64 tiles) ----
    const int m0 = (w >> 2) * 32, n0 = (w & 3) * 64;
    float c1[2][8][4];
    #pragma unroll
    for (int mi = 0; mi < 2; mi++)
        #pragma unroll
        for (int ni = 0; ni < 8; ni++)
            #pragma unroll
            for (int z = 0; z < 4; z++) c1[mi][ni][z] = 0.f;

    for (int ks = 0; ks < 16; ks++) {
        CPWAIT(1);
        __syncthreads();
        if (ks + 2 < 16) {
            int s = ks + 2;
            uint32_t d = sb + OFF_W1 + (s % 3) * 8320 + tid * 16;
            const char* src = (const char*)g_W1p + s * 8320 + tid * 16;
            CP16(d, src);
            if (tid < 8) CP16(d + 8192, src + 8192);
        }
        if (tid < 272) {   // W2 chunk ks (overlapped)
            uint32_t d = sb + OFF_W2 + ks * 4352 + tid * 16;
            const char* src = (const char*)g_W2p + ks * 4352 + tid * 16;
            CP16(d, src);
        }
        CPCOMMIT();

        const float* buf = (const float*)(smem + OFF_W1 + (ks % 3) * 8320);
        uint32_t a[2][4];
        #pragma unroll
        for (int mi = 0; mi < 2; mi++) {
            const float* xp = H + (m0 + mi * 16 + g) * S_X + ks * 8;
            a[mi][0] = fbits(xp[t]);
            a[mi][1] = fbits(xp[8 * S_X + t]);
            a[mi][2] = fbits(xp[t + 4]);
            a[mi][3] = fbits(xp[8 * S_X + t + 4]);
        }
        const float* bp = buf + t * 520 + n0 * 2 + g * 2;
        #pragma unroll
        for (int ni = 0; ni < 8; ni++) {
            float2 bv = *(const float2*)(bp + ni * 16);
            uint32_t b0 = fbits(bv.x), b1 = fbits(bv.y);
            mma8(c1[0][ni], a[0], b0, b1);
            mma8(c1[1][ni], a[1], b0, b1);
        }
    }
    CPWAIT(0);
    __syncthreads();

    // ---- epilogue 1: h = tf32(silu(D1 + Aq + Bk)) -> H (stride 260) ----
    #pragma unroll
    for (int mi = 0; mi < 2; mi++) {
        const int r0 = m0 + mi * 16 + g, r1 = r0 + 8;
        const float* bk0 = g_Bk + (size_t)(b * NK + kbase + r0) * DFF;
        const float* bk1 = g_Bk + (size_t)(b * NK + kbase + r1) * DFF;
        float2 e0[8], e1[8];
        #pragma unroll
        for (int ni = 0; ni < 8; ni++) {
            int f0 = n0 + 8 * ni + 2 * t;
            e0[ni] = *(const float2*)(bk0 + f0);
            e1[ni] = *(const float2*)(bk1 + f0);
        }
        #pragma unroll
        for (int ni = 0; ni < 8; ni++) {
            int f0 = n0 + 8 * ni + 2 * t;
            float2 aq = *(const float2*)(Aqs + f0);
            float v00 = c1[mi][ni][0] + aq.x + e0[ni].x;
            float v01 = c1[mi][ni][1] + aq.y + e0[ni].y;
            float v10 = c1[mi][ni][2] + aq.x + e1[ni].x;
            float v11 = c1[mi][ni][3] + aq.y + e1[ni].y;
            v00 = v00 / (1.f + __expf(-v00));
            v01 = v01 / (1.f + __expf(-v01));
            v10 = v10 / (1.f + __expf(-v10));
            v11 = v11 / (1.f + __expf(-v11));
            *(float2*)(H + r0 * S_H + f0) = make_float2(ftf32(v00), ftf32(v01));
            *(float2*)(H + r1 * S_H + f0) = make_float2(ftf32(v10), ftf32(v11));
        }
    }
    __syncthreads();

    // ---- GEMM2: [128x256] @ [256x64], warps 8M x 2N (16x32 tiles) ----
    const int m2 = (w >> 1) * 16, n2 = (w & 1) * 32;
    float c2[4][4];
    #pragma unroll
    for (int ni = 0; ni < 4; ni++)
        #pragma unroll
        for (int z = 0; z < 4; z++) c2[ni][z] = 0.f;

    #pragma unroll 4
    for (int ku = 0; ku < 32; ku++) {
        uint32_t a[4];
        const float* hp = H + (m2 + g) * S_H + ku * 8;
        a[0] = fbits(hp[t]);
        a[1] = fbits(hp[8 * S_H + t]);
        a[2] = fbits(hp[t + 4]);
        a[3] = fbits(hp[8 * S_H + t + 4]);
        const float* wp = W2s + ku * 544 + t * 136 + n2 * 2 + g * 2;
        #pragma unroll
        for (int ni = 0; ni < 4; ni++) {
            float2 bv = *(const float2*)(wp + ni * 16);
            mma8(c2[ni], a, fbits(bv.x), fbits(bv.y));
        }
    }

    // ---- epilogue 2: + b2 -> out ----
    const size_t obase = ((size_t)bq * NK + kbase) * DOUT;
    #pragma unroll
    for (int ni = 0; ni < 4; ni++) {
        int o = n2 + 8 * ni + 2 * t;
        int r0 = m2 + g, r1 = r0 + 8;
        *(float2*)(out + obase + (size_t)r0 * DOUT + o) =
            make_float2(c2[ni][0] + b2s[o], c2[ni][1] + b2s[o + 1]);
        *(float2*)(out + obase + (size_t)r1 * DOUT + o) =
            make_float2(c2[ni][2] + b2s[o], c2[ni][3] + b2s[o + 1]);
    }
}

// ---------------- launcher ----------------
extern "C" void kernel_launch(void* const* d_in, const int* in_sizes, int n_in,
                              void* d_out, int out_size) {
    const float* q_equi = (const float*)d_in[0];
    const float* q_inv  = (const float*)d_in[1];
    const float* k_equi = (const float*)d_in[2];
    const float* k_inv  = (const float*)d_in[3];
    const float* Wq     = (const float*)d_in[4];
    const float* bq     = (const float*)d_in[5];
    const float* Wk     = (const float*)d_in[6];
    const float* bk     = (const float*)d_in[7];
    const float* W1     = (const float*)d_in[8];
    const float* b1     = (const float*)d_in[9];
    const float* W2     = (const float*)d_in[10];
    const float* b2     = (const float*)d_in[11];
    float* out = (float*)d_out;

    cudaFuncSetAttribute(pm_main, cudaFuncAttributeMaxDynamicSharedMemorySize, SMEM_BYTES);

    prep_q<<<BB * NQ, 256>>>(q_inv, Wq, bq, W1, b1);
    prep_kb<<<BB * NK, 256>>>(k_inv, Wk, bk, W1);
    prep_pack<<<(16 * 4 * 520 + 32 * 4 * 136 + 255) / 256, 256>>>(W1, W2);
    pm_main<<<dim3(3, NQ, BB), 512, SMEM_BYTES>>>(q_equi, k_equi, b2, out);
}

// round 4
// speedup vs baseline: 2.0113x; 1.2722x over previous
#include <cuda_runtime.h>
#include <cuda_fp16.h>
#include <cstdint>
#include <math.h>

#define BB   4
#define NQ   384
#define NK   384
#define DQI  256
#define DKI  256
#define DM   64
#define DFF  256
#define DOUT 64

// byte strides (all 16B-multiples, mod 128 = 16 -> LDSM conflict-free)
#define SXB  272     // X row stride   (128 halves + 8 pad)
#define SHB  528     // h row stride   (256 halves + 8 pad)
#define SW2B 144     // W2 row stride  (64 halves + 8 pad)
#define W1_SLICE 8448   // 16 rows x 528 B
#define W2_BYTES 36864  // 256 rows x 144 B
#define W2_CHUNK 4608   // W2_BYTES / 8

#define OFF_H   0                      // 128 x 528 = 67584 (X view 128 x 272 inside)
#define OFF_W1  67584                  // 3 x 8448 = 25344
#define OFF_W2  92928                  // 36864
#define OFF_AQ  129792                 // 1024
#define OFF_QS  130816                 // 768
#define OFF_B2  131584                 // 256
#define SMEM_BYTES 131840

// ---------------- device scratch ----------------
__device__ float  g_Aq[BB * NQ * DFF];                    // fp32, exact
__device__ __align__(16) __half g_Bk[BB * NK * DFF];      // fp16
__device__ __align__(16) __half g_W1p[8 * 16 * 264];      // 8 slices [16][264]
__device__ __align__(16) __half g_W2p[256 * 72];          // [256][72]

// ---------------- helpers ----------------
__device__ __forceinline__ uint32_t smem_u32(const void* p) {
    uint32_t a;
    asm("{ .reg .u64 t; cvta.to.shared.u64 t, %1; cvt.u32.u64 %0, t; }" : "=r"(a) : "l"(p));
    return a;
}

__device__ __forceinline__ void ldsm4(uint32_t* r, uint32_t addr) {
    asm volatile("ldmatrix.sync.aligned.m8n8.x4.shared.b16 {%0,%1,%2,%3}, [%4];"
        : "=r"(r[0]), "=r"(r[1]), "=r"(r[2]), "=r"(r[3]) : "r"(addr));
}
__device__ __forceinline__ void ldsm4t(uint32_t* r, uint32_t addr) {
    asm volatile("ldmatrix.sync.aligned.m8n8.x4.trans.shared.b16 {%0,%1,%2,%3}, [%4];"
        : "=r"(r[0]), "=r"(r[1]), "=r"(r[2]), "=r"(r[3]) : "r"(addr));
}
__device__ __forceinline__ void mma16(float* d, const uint32_t* a, uint32_t b0, uint32_t b1) {
    asm volatile(
        "mma.sync.aligned.m16n8k16.row.col.f32.f16.f16.f32 "
        "{%0,%1,%2,%3}, {%4,%5,%6,%7}, {%8,%9}, {%0,%1,%2,%3};"
        : "+f"(d[0]), "+f"(d[1]), "+f"(d[2]), "+f"(d[3])
        : "r"(a[0]), "r"(a[1]), "r"(a[2]), "r"(a[3]), "r"(b0), "r"(b1));
}

#define CP16(d, s) asm volatile("cp.async.cg.shared.global [%0], [%1], 16;" :: "r"(d), "l"(s))
#define CPCOMMIT() asm volatile("cp.async.commit_group;")
#define CPWAIT(n)  asm volatile("cp.async.wait_group %0;" :: "n"(n))

// ---------------- prep kernels ----------------
__global__ void prep_q(const float* __restrict__ q_inv, const float* __restrict__ Wq,
                       const float* __restrict__ bq, const float* __restrict__ W1,
                       const float* __restrict__ b1) {
    const int bqi = blockIdx.x, tid = threadIdx.x;   // 256 threads
    __shared__ float sq[DQI];
    __shared__ float sm[DM];
    sq[tid] = q_inv[(size_t)bqi * DQI + tid];
    __syncthreads();
    if (tid < DM) {
        float a0 = 0.f, a1 = 0.f, a2 = 0.f, a3 = 0.f;
        #pragma unroll 16
        for (int i = 0; i < DQI; i += 4) {
            a0 += sq[i]     * Wq[(size_t)i * DM + tid];
            a1 += sq[i + 1] * Wq[(size_t)(i + 1) * DM + tid];
            a2 += sq[i + 2] * Wq[(size_t)(i + 2) * DM + tid];
            a3 += sq[i + 3] * Wq[(size_t)(i + 3) * DM + tid];
        }
        sm[tid] = bq[tid] + ((a0 + a1) + (a2 + a3));
    }
    __syncthreads();
    float a0 = 0.f, a1 = 0.f, a2 = 0.f, a3 = 0.f;
    #pragma unroll 16
    for (int m = 0; m < DM; m += 4) {
        a0 += sm[m]     * W1[(size_t)m * DFF + tid];
        a1 += sm[m + 1] * W1[(size_t)(m + 1) * DFF + tid];
        a2 += sm[m + 2] * W1[(size_t)(m + 2) * DFF + tid];
        a3 += sm[m + 3] * W1[(size_t)(m + 3) * DFF + tid];
    }
    g_Aq[(size_t)bqi * DFF + tid] = b1[tid] + ((a0 + a1) + (a2 + a3));
}

__global__ void prep_kb(const float* __restrict__ k_inv, const float* __restrict__ Wk,
                        const float* __restrict__ bk, const float* __restrict__ W1) {
    const int bki = blockIdx.x, tid = threadIdx.x;   // 256 threads
    __shared__ float sk[DKI];
    __shared__ float sm[DM];
    sk[tid] = k_inv[(size_t)bki * DKI + tid];
    __syncthreads();
    if (tid < DM) {
        float a0 = 0.f, a1 = 0.f, a2 = 0.f, a3 = 0.f;
        #pragma unroll 16
        for (int i = 0; i < DKI; i += 4) {
            a0 += sk[i]     * Wk[(size_t)i * DM + tid];
            a1 += sk[i + 1] * Wk[(size_t)(i + 1) * DM + tid];
            a2 += sk[i + 2] * Wk[(size_t)(i + 2) * DM + tid];
            a3 += sk[i + 3] * Wk[(size_t)(i + 3) * DM + tid];
        }
        sm[tid] = bk[tid] + ((a0 + a1) + (a2 + a3));
    }
    __syncthreads();
    float a0 = 0.f, a1 = 0.f, a2 = 0.f, a3 = 0.f;
    #pragma unroll 16
    for (int m = 0; m < DM; m += 4) {
        a0 += sm[m]     * W1[(size_t)(64 + m) * DFF + tid];
        a1 += sm[m + 1] * W1[(size_t)(65 + m) * DFF + tid];
        a2 += sm[m + 2] * W1[(size_t)(66 + m) * DFF + tid];
        a3 += sm[m + 3] * W1[(size_t)(67 + m) * DFF + tid];
    }
    g_Bk[(size_t)bki * DFF + tid] = __float2half_rn((a0 + a1) + (a2 + a3));
}

// pack W1[128:256,:] -> fp16 slices [8][16][264]; W2 -> fp16 [256][72]
__global__ void prep_pack(const float* __restrict__ W1, const float* __restrict__ W2) {
    const int gid = blockIdx.x * 256 + threadIdx.x;
    if (gid < 8 * 16 * 264) {
        int s = gid / 4224, r = gid % 4224, k = r / 264, n = r % 264;
        float v = (n < 256) ? W1[(size_t)(128 + s * 16 + k) * DFF + n] : 0.f;
        g_W1p[gid] = __float2half_rn(v);
    } else {
        int h = gid - 8 * 16 * 264;
        if (h < 256 * 72) {
            int k = h / 72, n = h % 72;
            float v = (n < 64) ? W2[(size_t)k * DOUT + n] : 0.f;
            g_W2p[h] = __float2half_rn(v);
        }
    }
}

// ---------------- main kernel: one CTA = (b, q, 128-k tile) ----------------
__global__ __launch_bounds__(512, 1)
void pm_main(const float* __restrict__ q_equi, const float* __restrict__ k_equi,
             const float* __restrict__ b2, float* __restrict__ out) {
    extern __shared__ char smem[];
    char* Hb = smem + OFF_H;
    float* Aqs = (float*)(smem + OFF_AQ);
    float* qs  = (float*)(smem + OFF_QS);
    float* b2s = (float*)(smem + OFF_B2);
    const uint32_t sb = smem_u32(smem);

    const int kb = blockIdx.x, q = blockIdx.y, b = blockIdx.z;
    const int kbase = kb * 128, bq = b * NQ + q;
    const int tid = threadIdx.x, w = tid >> 5, lane = tid & 31;
    const int g = lane >> 2, t = lane & 3;
    const int lrow = lane & 15, lsel = lane >> 4;   // ldmatrix lane addressing

    // ---- prologue: prefetch W1 slices 0,1 ----
    {
        const char* src = (const char*)g_W1p;
        uint32_t d0 = sb + OFF_W1 + tid * 16;
        CP16(d0, src + tid * 16);
        if (tid < 16) CP16(d0 + 8192, src + 8192 + tid * 16);
        CPCOMMIT();
        uint32_t d1 = sb + OFF_W1 + W1_SLICE + tid * 16;
        CP16(d1, src + W1_SLICE + tid * 16);
        if (tid < 16) CP16(d1 + 8192, src + W1_SLICE + 8192 + tid * 16);
        CPCOMMIT();
    }
    if (tid < 192) qs[tid] = q_equi[(size_t)bq * 192 + tid];
    if (tid < 256) Aqs[tid] = g_Aq[(size_t)bq * DFF + tid];
    else if (tid < 320) b2s[tid - 256] = b2[tid - 256];
    __syncthreads();

    // ---- build X = [dot | dist] (fp16), row stride 272 B ----
    {
        const int e = tid & 63, kk0 = tid >> 6;
        const float q0 = qs[e], q1 = qs[64 + e], q2 = qs[128 + e];
        const float qn2 = q0 * q0 + q1 * q1 + q2 * q2;
        const float* kp0 = k_equi + (size_t)(b * NK + kbase) * 192 + e;
        #pragma unroll 4
        for (int j = 0; j < 16; j++) {
            int kk = kk0 + j * 8;
            const float* kp = kp0 + (size_t)kk * 192;
            float k0 = kp[0], k1 = kp[64], k2 = kp[128];
            float dot = q0 * k0 + q1 * k1 + q2 * k2;
            float kn2 = k0 * k0 + k1 * k1 + k2 * k2;
            float dist = sqrtf(fmaxf(qn2 + kn2 - 2.f * dot, 0.f));
            *(__half*)(Hb + kk * SXB + e * 2)         = __float2half_rn(dot);
            *(__half*)(Hb + kk * SXB + 128 + e * 2)   = __float2half_rn(dist);
        }
    }
    // (visibility guaranteed by the __syncthreads at top of first GEMM1 iter)

    // ---- GEMM1: [128x128] @ [128x256] fp16, warps 4M x 4N (32x64 tiles) ----
    const int m0 = (w >> 2) * 32, n0 = (w & 3) * 64;
    float c1[2][8][4];
    #pragma unroll
    for (int mi = 0; mi < 2; mi++)
        #pragma unroll
        for (int ni = 0; ni < 8; ni++)
            #pragma unroll
            for (int z = 0; z < 4; z++) c1[mi][ni][z] = 0.f;

    const uint32_t aAddr = sb + OFF_H + (m0 + lrow) * SXB + lsel * 16;

    for (int ks = 0; ks < 8; ks++) {
        CPWAIT(1);
        __syncthreads();
        if (ks + 2 < 8) {
            int s = ks + 2;
            const char* src = (const char*)g_W1p + s * W1_SLICE;
            uint32_t d = sb + OFF_W1 + (s % 3) * W1_SLICE + tid * 16;
            CP16(d, src + tid * 16);
            if (tid < 16) CP16(d + 8192, src + 8192 + tid * 16);
        }
        if (tid < 288) {   // W2 chunk ks
            const char* src = (const char*)g_W2p + ks * W2_CHUNK;
            uint32_t d = sb + OFF_W2 + ks * W2_CHUNK + tid * 16;
            CP16(d, src + tid * 16);
        }
        CPCOMMIT();

        const uint32_t slot = sb + OFF_W1 + (ks % 3) * W1_SLICE;
        uint32_t a[2][4];
        ldsm4(a[0], aAddr + ks * 32);
        ldsm4(a[1], aAddr + 16 * SXB + ks * 32);
        #pragma unroll
        for (int p = 0; p < 4; p++) {
            uint32_t bb[4];
            ldsm4t(bb, slot + lrow * SHB + (n0 + p * 16 + lsel * 8) * 2);
            mma16(c1[0][2 * p],     a[0], bb[0], bb[1]);
            mma16(c1[1][2 * p],     a[1], bb[0], bb[1]);
            mma16(c1[0][2 * p + 1], a[0], bb[2], bb[3]);
            mma16(c1[1][2 * p + 1], a[1], bb[2], bb[3]);
        }
    }
    CPWAIT(0);
    __syncthreads();

    // ---- epilogue 1: h = fp16(silu(D1 + Aq + Bk)) -> H (stride 528 B) ----
    #pragma unroll
    for (int mi = 0; mi < 2; mi++) {
        const int r0 = m0 + mi * 16 + g, r1 = r0 + 8;
        const __half2* bk0 = (const __half2*)(g_Bk + (size_t)(b * NK + kbase + r0) * DFF);
        const __half2* bk1 = (const __half2*)(g_Bk + (size_t)(b * NK + kbase + r1) * DFF);
        float2 e0[8], e1[8];
        #pragma unroll
        for (int ni = 0; ni < 8; ni++) {
            int c2i = (n0 >> 1) + 4 * ni + t;
            e0[ni] = __half22float2(bk0[c2i]);
            e1[ni] = __half22float2(bk1[c2i]);
        }
        #pragma unroll
        for (int ni = 0; ni < 8; ni++) {
            int f0 = n0 + 8 * ni + 2 * t;
            float2 aq = *(const float2*)(Aqs + f0);
            float v00 = c1[mi][ni][0] + aq.x + e0[ni].x;
            float v01 = c1[mi][ni][1] + aq.y + e0[ni].y;
            float v10 = c1[mi][ni][2] + aq.x + e1[ni].x;
            float v11 = c1[mi][ni][3] + aq.y + e1[ni].y;
            v00 = v00 / (1.f + __expf(-v00));
            v01 = v01 / (1.f + __expf(-v01));
            v10 = v10 / (1.f + __expf(-v10));
            v11 = v11 / (1.f + __expf(-v11));
            *(__half2*)(Hb + r0 * SHB + f0 * 2) = __floats2half2_rn(v00, v01);
            *(__half2*)(Hb + r1 * SHB + f0 * 2) = __floats2half2_rn(v10, v11);
        }
    }
    __syncthreads();

    // ---- GEMM2: [128x256] @ [256x64] fp16, warps 8M x 2N (16x32 tiles) ----
    const int m2 = (w >> 1) * 16, n2 = (w & 1) * 32;
    float c2[4][4];
    #pragma unroll
    for (int ni = 0; ni < 4; ni++)
        #pragma unroll
        for (int z = 0; z < 4; z++) c2[ni][z] = 0.f;

    const uint32_t a2Addr = sb + OFF_H + (m2 + lrow) * SHB + lsel * 16;
    #pragma unroll 4
    for (int ks = 0; ks < 16; ks++) {
        uint32_t a[4];
        ldsm4(a, a2Addr + ks * 32);
        #pragma unroll
        for (int p = 0; p < 2; p++) {
            uint32_t bb[4];
            ldsm4t(bb, sb + OFF_W2 + (ks * 16 + lrow) * SW2B + (n2 + p * 16 + lsel * 8) * 2);
            mma16(c2[2 * p],     a, bb[0], bb[1]);
            mma16(c2[2 * p + 1], a, bb[2], bb[3]);
        }
    }

    // ---- epilogue 2: + b2 -> out ----
    const size_t obase = ((size_t)bq * NK + kbase) * DOUT;
    #pragma unroll
    for (int ni = 0; ni < 4; ni++) {
        int o = n2 + 8 * ni + 2 * t;
        int r0 = m2 + g, r1 = r0 + 8;
        *(float2*)(out + obase + (size_t)r0 * DOUT + o) =
            make_float2(c2[ni][0] + b2s[o], c2[ni][1] + b2s[o + 1]);
        *(float2*)(out + obase + (size_t)r1 * DOUT + o) =
            make_float2(c2[ni][2] + b2s[o], c2[ni][3] + b2s[o + 1]);
    }
}

// ---------------- launcher ----------------
extern "C" void kernel_launch(void* const* d_in, const int* in_sizes, int n_in,
                              void* d_out, int out_size) {
    const float* q_equi = (const float*)d_in[0];
    const float* q_inv  = (const float*)d_in[1];
    const float* k_equi = (const float*)d_in[2];
    const float* k_inv  = (const float*)d_in[3];
    const float* Wq     = (const float*)d_in[4];
    const float* bq     = (const float*)d_in[5];
    const float* Wk     = (const float*)d_in[6];
    const float* bk     = (const float*)d_in[7];
    const float* W1     = (const float*)d_in[8];
    const float* b1     = (const float*)d_in[9];
    const float* W2     = (const float*)d_in[10];
    const float* b2     = (const float*)d_in[11];
    float* out = (float*)d_out;

    cudaFuncSetAttribute(pm_main, cudaFuncAttributeMaxDynamicSharedMemorySize, SMEM_BYTES);

    prep_q<<<BB * NQ, 256>>>(q_inv, Wq, bq, W1, b1);
    prep_kb<<<BB * NK, 256>>>(k_inv, Wk, bk, W1);
    prep_pack<<<(8 * 16 * 264 + 256 * 72 + 255) / 256, 256>>>(W1, W2);
    pm_main<<<dim3(3, NQ, BB), 512, SMEM_BYTES>>>(q_equi, k_equi, b2, out);
}

// round 5
// speedup vs baseline: 2.3554x; 1.1711x over previous
#include <cuda_runtime.h>
#include <cuda_fp16.h>
#include <cstdint>
#include <math.h>

#define BB   4
#define NQ   384
#define NK   384
#define DQI  256
#define DKI  256
#define DM   64
#define DFF  256
#define DOUT 64
#define KT   64      // k-rows per CTA

// byte strides (16B-multiples, mod 128 = 16 -> LDSM conflict-free)
#define SXB  272     // X row stride   (128 halves + 8 pad)
#define SHB  528     // h row stride   (256 halves + 8 pad)
#define SW2B 144     // W2 row stride  (64 halves + 8 pad)
#define W1_SLICE 8448   // 16 rows x 528 B
#define W2_BYTES 36864  // 256 rows x 144 B
#define W2_CHUNK 4608   // W2_BYTES / 8

#define OFF_H   0                      // 64 x 528 = 33792 (X view 64 x 272 inside)
#define OFF_W1  33792                  // 3 x 8448 = 25344
#define OFF_W2  59136                  // 36864
#define OFF_AQ  96000                  // 1024
#define OFF_QS  97024                  // 768
#define OFF_B2  97792                  // 256
#define SMEM_BYTES 98048

// ---------------- device scratch ----------------
__device__ float  g_Aq[BB * NQ * DFF];                    // fp32, exact
__device__ __align__(16) __half g_Bk[BB * NK * DFF];      // fp16
__device__ __align__(16) __half g_W1p[8 * 16 * 264];      // 8 slices [16][264]
__device__ __align__(16) __half g_W2p[256 * 72];          // [256][72]

// ---------------- helpers ----------------
__device__ __forceinline__ uint32_t smem_u32(const void* p) {
    uint32_t a;
    asm("{ .reg .u64 t; cvta.to.shared.u64 t, %1; cvt.u32.u64 %0, t; }" : "=r"(a) : "l"(p));
    return a;
}
__device__ __forceinline__ void ldsm4(uint32_t* r, uint32_t addr) {
    asm volatile("ldmatrix.sync.aligned.m8n8.x4.shared.b16 {%0,%1,%2,%3}, [%4];"
        : "=r"(r[0]), "=r"(r[1]), "=r"(r[2]), "=r"(r[3]) : "r"(addr));
}
__device__ __forceinline__ void ldsm4t(uint32_t* r, uint32_t addr) {
    asm volatile("ldmatrix.sync.aligned.m8n8.x4.trans.shared.b16 {%0,%1,%2,%3}, [%4];"
        : "=r"(r[0]), "=r"(r[1]), "=r"(r[2]), "=r"(r[3]) : "r"(addr));
}
__device__ __forceinline__ void mma16(float* d, const uint32_t* a, uint32_t b0, uint32_t b1) {
    asm volatile(
        "mma.sync.aligned.m16n8k16.row.col.f32.f16.f16.f32 "
        "{%0,%1,%2,%3}, {%4,%5,%6,%7}, {%8,%9}, {%0,%1,%2,%3};"
        : "+f"(d[0]), "+f"(d[1]), "+f"(d[2]), "+f"(d[3])
        : "r"(a[0]), "r"(a[1]), "r"(a[2]), "r"(a[3]), "r"(b0), "r"(b1));
}

#define CP16(d, s) asm volatile("cp.async.cg.shared.global [%0], [%1], 16;" :: "r"(d), "l"(s))
#define CPCOMMIT() asm volatile("cp.async.commit_group;")
#define CPWAIT(n)  asm volatile("cp.async.wait_group %0;" :: "n"(n))

// ---------------- prep kernels ----------------
__global__ void prep_q(const float* __restrict__ q_inv, const float* __restrict__ Wq,
                       const float* __restrict__ bq, const float* __restrict__ W1,
                       const float* __restrict__ b1) {
    const int bqi = blockIdx.x, tid = threadIdx.x;   // 256 threads
    __shared__ float sq[DQI];
    __shared__ float sm[DM];
    sq[tid] = q_inv[(size_t)bqi * DQI + tid];
    __syncthreads();
    if (tid < DM) {
        float a0 = 0.f, a1 = 0.f, a2 = 0.f, a3 = 0.f;
        #pragma unroll 16
        for (int i = 0; i < DQI; i += 4) {
            a0 += sq[i]     * Wq[(size_t)i * DM + tid];
            a1 += sq[i + 1] * Wq[(size_t)(i + 1) * DM + tid];
            a2 += sq[i + 2] * Wq[(size_t)(i + 2) * DM + tid];
            a3 += sq[i + 3] * Wq[(size_t)(i + 3) * DM + tid];
        }
        sm[tid] = bq[tid] + ((a0 + a1) + (a2 + a3));
    }
    __syncthreads();
    float a0 = 0.f, a1 = 0.f, a2 = 0.f, a3 = 0.f;
    #pragma unroll 16
    for (int m = 0; m < DM; m += 4) {
        a0 += sm[m]     * W1[(size_t)m * DFF + tid];
        a1 += sm[m + 1] * W1[(size_t)(m + 1) * DFF + tid];
        a2 += sm[m + 2] * W1[(size_t)(m + 2) * DFF + tid];
        a3 += sm[m + 3] * W1[(size_t)(m + 3) * DFF + tid];
    }
    g_Aq[(size_t)bqi * DFF + tid] = b1[tid] + ((a0 + a1) + (a2 + a3));
}

__global__ void prep_kb(const float* __restrict__ k_inv, const float* __restrict__ Wk,
                        const float* __restrict__ bk, const float* __restrict__ W1) {
    const int bki = blockIdx.x, tid = threadIdx.x;   // 256 threads
    __shared__ float sk[DKI];
    __shared__ float sm[DM];
    sk[tid] = k_inv[(size_t)bki * DKI + tid];
    __syncthreads();
    if (tid < DM) {
        float a0 = 0.f, a1 = 0.f, a2 = 0.f, a3 = 0.f;
        #pragma unroll 16
        for (int i = 0; i < DKI; i += 4) {
            a0 += sk[i]     * Wk[(size_t)i * DM + tid];
            a1 += sk[i + 1] * Wk[(size_t)(i + 1) * DM + tid];
            a2 += sk[i + 2] * Wk[(size_t)(i + 2) * DM + tid];
            a3 += sk[i + 3] * Wk[(size_t)(i + 3) * DM + tid];
        }
        sm[tid] = bk[tid] + ((a0 + a1) + (a2 + a3));
    }
    __syncthreads();
    float a0 = 0.f, a1 = 0.f, a2 = 0.f, a3 = 0.f;
    #pragma unroll 16
    for (int m = 0; m < DM; m += 4) {
        a0 += sm[m]     * W1[(size_t)(64 + m) * DFF + tid];
        a1 += sm[m + 1] * W1[(size_t)(65 + m) * DFF + tid];
        a2 += sm[m + 2] * W1[(size_t)(66 + m) * DFF + tid];
        a3 += sm[m + 3] * W1[(size_t)(67 + m) * DFF + tid];
    }
    g_Bk[(size_t)bki * DFF + tid] = __float2half_rn((a0 + a1) + (a2 + a3));
}

// pack W1[128:256,:] -> fp16 slices [8][16][264]; W2 -> fp16 [256][72]
__global__ void prep_pack(const float* __restrict__ W1, const float* __restrict__ W2) {
    const int gid = blockIdx.x * 256 + threadIdx.x;
    if (gid < 8 * 16 * 264) {
        int s = gid / 4224, r = gid % 4224, k = r / 264, n = r % 264;
        float v = (n < 256) ? W1[(size_t)(128 + s * 16 + k) * DFF + n] : 0.f;
        g_W1p[gid] = __float2half_rn(v);
    } else {
        int h = gid - 8 * 16 * 264;
        if (h < 256 * 72) {
            int k = h / 72, n = h % 72;
            float v = (n < 64) ? W2[(size_t)k * DOUT + n] : 0.f;
            g_W2p[h] = __float2half_rn(v);
        }
    }
}

// ---------------- main kernel: one CTA = (b, q, 64-k tile), 2 CTAs/SM ----------------
__global__ __launch_bounds__(256, 2)
void pm_main(const float* __restrict__ q_equi, const float* __restrict__ k_equi,
             const float* __restrict__ b2, float* __restrict__ out) {
    extern __shared__ char smem[];
    char* Hb = smem + OFF_H;
    float* Aqs = (float*)(smem + OFF_AQ);
    float* qs  = (float*)(smem + OFF_QS);
    float* b2s = (float*)(smem + OFF_B2);
    const uint32_t sb = smem_u32(smem);

    const int kb = blockIdx.x, q = blockIdx.y, b = blockIdx.z;
    const int kbase = kb * KT, bq = b * NQ + q;
    const int tid = threadIdx.x, w = tid >> 5, lane = tid & 31;
    const int g = lane >> 2, t = lane & 3;
    const int lrow = lane & 15, lsel = lane >> 4;

    // ---- prologue: prefetch W1 slices 0,1 ----
    {
        const char* src = (const char*)g_W1p;
        uint32_t d0 = sb + OFF_W1 + tid * 16;
        CP16(d0, src + tid * 16);
        CP16(d0 + 4096, src + 4096 + tid * 16);
        if (tid < 16) CP16(d0 + 8192, src + 8192 + tid * 16);
        CPCOMMIT();
        uint32_t d1 = sb + OFF_W1 + W1_SLICE + tid * 16;
        const char* s1 = src + W1_SLICE;
        CP16(d1, s1 + tid * 16);
        CP16(d1 + 4096, s1 + 4096 + tid * 16);
        if (tid < 16) CP16(d1 + 8192, s1 + 8192 + tid * 16);
        CPCOMMIT();
    }
    if (tid < 192) qs[tid] = q_equi[(size_t)bq * 192 + tid];
    Aqs[tid] = g_Aq[(size_t)bq * DFF + tid];
    if (tid < 64) b2s[tid] = b2[tid];
    __syncthreads();

    // ---- build X = [dot | dist] (fp16), 64 rows, stride 272 B ----
    {
        const int e = tid & 63, kk0 = tid >> 6;   // kk0 in 0..3
        const float q0 = qs[e], q1 = qs[64 + e], q2 = qs[128 + e];
        const float qn2 = q0 * q0 + q1 * q1 + q2 * q2;
        const float* kp0 = k_equi + (size_t)(b * NK + kbase) * 192 + e;
        #pragma unroll 4
        for (int j = 0; j < 16; j++) {
            int kk = kk0 + j * 4;
            const float* kp = kp0 + (size_t)kk * 192;
            float k0 = kp[0], k1 = kp[64], k2 = kp[128];
            float dot = q0 * k0 + q1 * k1 + q2 * k2;
            float kn2 = k0 * k0 + k1 * k1 + k2 * k2;
            float dist = sqrtf(fmaxf(qn2 + kn2 - 2.f * dot, 0.f));
            *(__half*)(Hb + kk * SXB + e * 2)       = __float2half_rn(dot);
            *(__half*)(Hb + kk * SXB + 128 + e * 2) = __float2half_rn(dist);
        }
    }
    // visibility via the __syncthreads at top of first GEMM1 iter

    // ---- GEMM1: [64x128] @ [128x256] fp16, warps 2M x 4N (32x64 tiles) ----
    const int m0 = (w >> 2) * 32, n0 = (w & 3) * 64;
    float c1[2][8][4];
    #pragma unroll
    for (int mi = 0; mi < 2; mi++)
        #pragma unroll
        for (int ni = 0; ni < 8; ni++)
            #pragma unroll
            for (int z = 0; z < 4; z++) c1[mi][ni][z] = 0.f;

    const uint32_t aAddr = sb + OFF_H + (m0 + lrow) * SXB + lsel * 16;

    for (int ks = 0; ks < 8; ks++) {
        CPWAIT(1);
        __syncthreads();
        if (ks + 2 < 8) {
            int s = ks + 2;
            const char* src = (const char*)g_W1p + s * W1_SLICE;
            uint32_t d = sb + OFF_W1 + (s % 3) * W1_SLICE + tid * 16;
            CP16(d, src + tid * 16);
            CP16(d + 4096, src + 4096 + tid * 16);
            if (tid < 16) CP16(d + 8192, src + 8192 + tid * 16);
        }
        {   // W2 chunk ks
            const char* src = (const char*)g_W2p + ks * W2_CHUNK;
            uint32_t d = sb + OFF_W2 + ks * W2_CHUNK + tid * 16;
            CP16(d, src + tid * 16);
            if (tid < 32) CP16(d + 4096, src + 4096 + tid * 16);
        }
        CPCOMMIT();

        const uint32_t slot = sb + OFF_W1 + (ks % 3) * W1_SLICE;
        uint32_t a[2][4];
        ldsm4(a[0], aAddr + ks * 32);
        ldsm4(a[1], aAddr + 16 * SXB + ks * 32);
        #pragma unroll
        for (int p = 0; p < 4; p++) {
            uint32_t bb[4];
            ldsm4t(bb, slot + lrow * SHB + (n0 + p * 16 + lsel * 8) * 2);
            mma16(c1[0][2 * p],     a[0], bb[0], bb[1]);
            mma16(c1[1][2 * p],     a[1], bb[0], bb[1]);
            mma16(c1[0][2 * p + 1], a[0], bb[2], bb[3]);
            mma16(c1[1][2 * p + 1], a[1], bb[2], bb[3]);
        }
    }
    CPWAIT(0);
    __syncthreads();

    // ---- epilogue 1: h = fp16(silu(D1 + Aq + Bk)) -> H (stride 528 B) ----
    #pragma unroll
    for (int mi = 0; mi < 2; mi++) {
        const int r0 = m0 + mi * 16 + g, r1 = r0 + 8;
        const __half2* bk0 = (const __half2*)(g_Bk + (size_t)(b * NK + kbase + r0) * DFF);
        const __half2* bk1 = (const __half2*)(g_Bk + (size_t)(b * NK + kbase + r1) * DFF);
        float2 e0[8], e1[8];
        #pragma unroll
        for (int ni = 0; ni < 8; ni++) {
            int c2i = (n0 >> 1) + 4 * ni + t;
            e0[ni] = __half22float2(bk0[c2i]);
            e1[ni] = __half22float2(bk1[c2i]);
        }
        #pragma unroll
        for (int ni = 0; ni < 8; ni++) {
            int f0 = n0 + 8 * ni + 2 * t;
            float2 aq = *(const float2*)(Aqs + f0);
            float v00 = c1[mi][ni][0] + aq.x + e0[ni].x;
            float v01 = c1[mi][ni][1] + aq.y + e0[ni].y;
            float v10 = c1[mi][ni][2] + aq.x + e1[ni].x;
            float v11 = c1[mi][ni][3] + aq.y + e1[ni].y;
            v00 = v00 / (1.f + __expf(-v00));
            v01 = v01 / (1.f + __expf(-v01));
            v10 = v10 / (1.f + __expf(-v10));
            v11 = v11 / (1.f + __expf(-v11));
            *(__half2*)(Hb + r0 * SHB + f0 * 2) = __floats2half2_rn(v00, v01);
            *(__half2*)(Hb + r1 * SHB + f0 * 2) = __floats2half2_rn(v10, v11);
        }
    }
    __syncthreads();

    // ---- GEMM2: [64x256] @ [256x64] fp16, warps 4M x 2N (16x32 tiles) ----
    const int m2 = (w >> 1) * 16, n2 = (w & 1) * 32;
    float c2[4][4];
    #pragma unroll
    for (int ni = 0; ni < 4; ni++)
        #pragma unroll
        for (int z = 0; z < 4; z++) c2[ni][z] = 0.f;

    const uint32_t a2Addr = sb + OFF_H + (m2 + lrow) * SHB + lsel * 16;
    #pragma unroll 4
    for (int ks = 0; ks < 16; ks++) {
        uint32_t a[4];
        ldsm4(a, a2Addr + ks * 32);
        #pragma unroll
        for (int p = 0; p < 2; p++) {
            uint32_t bb[4];
            ldsm4t(bb, sb + OFF_W2 + (ks * 16 + lrow) * SW2B + (n2 + p * 16 + lsel * 8) * 2);
            mma16(c2[2 * p],     a, bb[0], bb[1]);
            mma16(c2[2 * p + 1], a, bb[2], bb[3]);
        }
    }

    // ---- epilogue 2: + b2 -> out ----
    const size_t obase = ((size_t)bq * NK + kbase) * DOUT;
    #pragma unroll
    for (int ni = 0; ni < 4; ni++) {
        int o = n2 + 8 * ni + 2 * t;
        int r0 = m2 + g, r1 = r0 + 8;
        *(float2*)(out + obase + (size_t)r0 * DOUT + o) =
            make_float2(c2[ni][0] + b2s[o], c2[ni][1] + b2s[o + 1]);
        *(float2*)(out + obase + (size_t)r1 * DOUT + o) =
            make_float2(c2[ni][2] + b2s[o], c2[ni][3] + b2s[o + 1]);
    }
}

// ---------------- launcher ----------------
extern "C" void kernel_launch(void* const* d_in, const int* in_sizes, int n_in,
                              void* d_out, int out_size) {
    const float* q_equi = (const float*)d_in[0];
    const float* q_inv  = (const float*)d_in[1];
    const float* k_equi = (const float*)d_in[2];
    const float* k_inv  = (const float*)d_in[3];
    const float* Wq     = (const float*)d_in[4];
    const float* bq     = (const float*)d_in[5];
    const float* Wk     = (const float*)d_in[6];
    const float* bk     = (const float*)d_in[7];
    const float* W1     = (const float*)d_in[8];
    const float* b1     = (const float*)d_in[9];
    const float* W2     = (const float*)d_in[10];
    const float* b2     = (const float*)d_in[11];
    float* out = (float*)d_out;

    cudaFuncSetAttribute(pm_main, cudaFuncAttributeMaxDynamicSharedMemorySize, SMEM_BYTES);

    prep_q<<<BB * NQ, 256>>>(q_inv, Wq, bq, W1, b1);
    prep_kb<<<BB * NK, 256>>>(k_inv, Wk, bk, W1);
    prep_pack<<<(8 * 16 * 264 + 256 * 72 + 255) / 256, 256>>>(W1, W2);
    pm_main<<<dim3(NK / KT, NQ, BB), 256, SMEM_BYTES>>>(q_equi, k_equi, b2, out);
}